// round 3
// baseline (speedup 1.0000x reference)
#include <cuda_runtime.h>

#define NB 16
#define NC 3
#define IH 720
#define IW 1280
#define OUT 255
#define PER_B (NC*IH*IW)          /* 2764800 floats per batch image */
#define PER_B4 (PER_B/4)          /* 691200 float4 per batch image */
#define RBLK 64                   /* reduction blocks per batch */
#define PIX_PER_B (NC*OUT*OUT)    /* 195075 output pixels per batch */
#define TOTAL (NB*PIX_PER_B)      /* 3121200 */

__device__ float d_partial[NB * RBLK];

// ---------------------------------------------------------------------------
// Kernel 1: per-batch partial sums. grid = (RBLK, NB), block = 256.
// Unroll x4 with independent accumulators -> 4 LDG.128 in flight per iter.
// ---------------------------------------------------------------------------
__global__ void reduce_kernel(const float* __restrict__ im) {
    const int b   = blockIdx.y;
    const int blk = blockIdx.x;
    const float4* __restrict__ p = (const float4*)(im + (size_t)b * PER_B);

    const int stride = RBLK * 256;            /* 16384 */
    int i = blk * 256 + threadIdx.x;

    float a0 = 0.f, a1 = 0.f, a2 = 0.f, a3 = 0.f;
    for (; i + 3 * stride < PER_B4; i += 4 * stride) {
        float4 v0 = p[i];
        float4 v1 = p[i + stride];
        float4 v2 = p[i + 2 * stride];
        float4 v3 = p[i + 3 * stride];
        a0 += (v0.x + v0.y) + (v0.z + v0.w);
        a1 += (v1.x + v1.y) + (v1.z + v1.w);
        a2 += (v2.x + v2.y) + (v2.z + v2.w);
        a3 += (v3.x + v3.y) + (v3.z + v3.w);
    }
    for (; i < PER_B4; i += stride) {
        float4 v = p[i];
        a0 += (v.x + v.y) + (v.z + v.w);
    }
    float s = (a0 + a1) + (a2 + a3);

    __shared__ float sm[256];
    sm[threadIdx.x] = s;
    __syncthreads();
    for (int o = 128; o > 0; o >>= 1) {
        if (threadIdx.x < o) sm[threadIdx.x] += sm[threadIdx.x + o];
        __syncthreads();
    }
    if (threadIdx.x == 0) d_partial[b * RBLK + blk] = sm[0];
}

// ---------------------------------------------------------------------------
// Common per-pixel coordinate math (identical expressions in both kernels so
// the fp values match exactly between main blend and patch).
// ---------------------------------------------------------------------------
struct Coords {
    float y0, y1, x0, x1, wx, wy;
    int b, c;
    int idx;
};

__device__ __forceinline__ Coords compute_coords(int idx,
                                                 const float* __restrict__ pos,
                                                 const float* __restrict__ szs) {
    Coords r;
    r.idx = idx;
    int ox = idx % OUT;
    int t  = idx / OUT;
    int oy = t % OUT;
    t /= OUT;
    r.c = t % NC;
    r.b = t / NC;

    const float sz    = __ldg(&szs[r.b]);
    const float half  = (sz + 1.0f) * 0.5f;
    const float xmin  = rintf(__ldg(&pos[2 * r.b + 0]) - half);
    const float ymin  = rintf(__ldg(&pos[2 * r.b + 1]) - half);
    const float scale = sz / (float)OUT;
    const float szm1  = sz - 1.0f;

    float sx = fminf(fmaxf(((float)ox + 0.5f) * scale - 0.5f, 0.0f), szm1);
    float lx = floorf(sx);
    r.wx = sx - lx;
    float hx = fminf(lx + 1.0f, szm1);

    float sy = fminf(fmaxf(((float)oy + 0.5f) * scale - 0.5f, 0.0f), szm1);
    float ly = floorf(sy);
    r.wy = sy - ly;
    float hy = fminf(ly + 1.0f, szm1);

    r.y0 = ly + ymin; r.y1 = hy + ymin;
    r.x0 = lx + xmin; r.x1 = hx + xmin;
    return r;
}

__device__ __forceinline__ bool corner_valid(float yf, float xf) {
    return (yf >= 0.0f) & (yf <= (float)(IH - 1)) &
           (xf >= 0.0f) & (xf <= (float)(IW - 1));
}

// ---------------------------------------------------------------------------
// Kernel 2 (forked branch, overlaps reduce): blend of VALID corners only
// (invalid corners contribute 0). No dependence on the mean.
// ---------------------------------------------------------------------------
__global__ void bilinear_main_kernel(const float* __restrict__ im,
                                     const float* __restrict__ pos,
                                     const float* __restrict__ szs,
                                     float* __restrict__ out) {
    const int idx = blockIdx.x * blockDim.x + threadIdx.x;
    if (idx >= TOTAL) return;

    Coords r = compute_coords(idx, pos, szs);
    const float* base = im + ((size_t)r.b * NC + r.c) * (size_t)(IH * IW);

    auto gather0 = [&](float yf, float xf) -> float {
        bool v = corner_valid(yf, xf);
        int yc = (int)fminf(fmaxf(yf, 0.0f), (float)(IH - 1));
        int xc = (int)fminf(fmaxf(xf, 0.0f), (float)(IW - 1));
        float pix = __ldg(&base[yc * IW + xc]);
        return v ? pix : 0.0f;
    };

    float v00 = gather0(r.y0, r.x0);
    float v01 = gather0(r.y0, r.x1);
    float v10 = gather0(r.y1, r.x0);
    float v11 = gather0(r.y1, r.x1);

    float top = v00 * (1.0f - r.wx) + v01 * r.wx;
    float bot = v10 * (1.0f - r.wx) + v11 * r.wx;
    out[idx]  = top * (1.0f - r.wy) + bot * r.wy;
}

// ---------------------------------------------------------------------------
// Kernel 3 (joins both branches): computes per-batch means from partials
// (first two warps, covers the <=2 batches this block touches) and adds
// avg * (total weight of invalid corners) to OOB-affected pixels only.
// ---------------------------------------------------------------------------
__global__ void patch_kernel(const float* __restrict__ pos,
                             const float* __restrict__ szs,
                             float* __restrict__ out) {
    __shared__ float s_mean[2];

    const int first = blockIdx.x * blockDim.x;
    const int last  = min(first + (int)blockDim.x - 1, TOTAL - 1);
    const int b0 = first / PIX_PER_B;
    const int b1 = last  / PIX_PER_B;

    const int w = threadIdx.x >> 5;
    const int l = threadIdx.x & 31;
    if (w < 2) {
        const int b = (w == 0) ? b0 : b1;
        float s = d_partial[b * RBLK + l] + d_partial[b * RBLK + 32 + l];
        #pragma unroll
        for (int o = 16; o > 0; o >>= 1) s += __shfl_down_sync(0xffffffffu, s, o);
        if (l == 0) s_mean[w] = s * (1.0f / (float)PER_B);
    }
    __syncthreads();

    const int idx = first + threadIdx.x;
    if (idx >= TOTAL) return;

    Coords r = compute_coords(idx, pos, szs);

    bool i00 = !corner_valid(r.y0, r.x0);
    bool i01 = !corner_valid(r.y0, r.x1);
    bool i10 = !corner_valid(r.y1, r.x0);
    bool i11 = !corner_valid(r.y1, r.x1);

    if (i00 | i01 | i10 | i11) {
        float w00 = (1.0f - r.wx) * (1.0f - r.wy);
        float w01 = r.wx * (1.0f - r.wy);
        float w10 = (1.0f - r.wx) * r.wy;
        float w11 = r.wx * r.wy;
        float w_inv = (i00 ? w00 : 0.0f) + (i01 ? w01 : 0.0f) +
                      (i10 ? w10 : 0.0f) + (i11 ? w11 : 0.0f);
        float avg = (r.b == b0) ? s_mean[0] : s_mean[1];
        out[idx] += w_inv * avg;
    }
}

// ---------------------------------------------------------------------------
extern "C" void kernel_launch(void* const* d_in, const int* in_sizes, int n_in,
                              void* d_out, int out_size) {
    const float* im  = (const float*)d_in[0];
    const float* pos = (const float*)d_in[1];
    const float* szs = (const float*)d_in[2];
    float* out = (float*)d_out;

    // Fork a side stream so bilinear_main overlaps the reduce in the graph.
    cudaStream_t s2;
    cudaEvent_t e_fork, e_join;
    cudaStreamCreateWithFlags(&s2, cudaStreamNonBlocking);
    cudaEventCreateWithFlags(&e_fork, cudaEventDisableTiming);
    cudaEventCreateWithFlags(&e_join, cudaEventDisableTiming);

    cudaEventRecord(e_fork, 0);
    cudaStreamWaitEvent(s2, e_fork, 0);

    // Branch A (default stream): full-image mean partials.
    reduce_kernel<<<dim3(RBLK, NB), 256>>>(im);

    // Branch B (s2): valid-corner bilinear blend (independent of the mean).
    const int blocks = (TOTAL + 255) / 256;
    bilinear_main_kernel<<<blocks, 256, 0, s2>>>(im, pos, szs, out);
    cudaEventRecord(e_join, s2);

    // Join: patch OOB pixels with mean contribution (also finalizes means).
    cudaStreamWaitEvent(0, e_join, 0);
    patch_kernel<<<blocks, 256>>>(pos, szs, out);
    // Streams/events intentionally not destroyed: kernel_launch is only called
    // a handful of times (correctness + capture); replays re-run the graph only.
}

// round 4
// speedup vs baseline: 1.0929x; 1.0929x over previous
#include <cuda_runtime.h>

#define NB 16
#define NC 3
#define IH 720
#define IW 1280
#define OUT 255
#define PER_B (NC*IH*IW)          /* 2764800 floats per batch image */
#define PER_B4 (PER_B/4)          /* 691200 float4 per batch image */
#define RBLK 74                   /* reduction blocks per batch -> 1184 = 8*148 total */
#define PIX_PER_B (NC*OUT*OUT)    /* 195075 output pixels per batch */
#define TOTAL (NB*PIX_PER_B)      /* 3121200 */

__device__ float d_partial[NB * RBLK];

// ---------------------------------------------------------------------------
// Kernel 1: per-batch partial sums. grid = (RBLK, NB) = 1184 blocks, block=256.
// One full-occupancy wave on 148 SMs. Unroll x4, independent accumulators.
// ---------------------------------------------------------------------------
__global__ void reduce_kernel(const float* __restrict__ im) {
    const int b   = blockIdx.y;
    const int blk = blockIdx.x;
    const float4* __restrict__ p = (const float4*)(im + (size_t)b * PER_B);

    const int stride = RBLK * 256;            /* 18944 */
    int i = blk * 256 + threadIdx.x;

    float a0 = 0.f, a1 = 0.f, a2 = 0.f, a3 = 0.f;
    for (; i + 3 * stride < PER_B4; i += 4 * stride) {
        float4 v0 = p[i];
        float4 v1 = p[i + stride];
        float4 v2 = p[i + 2 * stride];
        float4 v3 = p[i + 3 * stride];
        a0 += (v0.x + v0.y) + (v0.z + v0.w);
        a1 += (v1.x + v1.y) + (v1.z + v1.w);
        a2 += (v2.x + v2.y) + (v2.z + v2.w);
        a3 += (v3.x + v3.y) + (v3.z + v3.w);
    }
    for (; i < PER_B4; i += stride) {
        float4 v = p[i];
        a0 += (v.x + v.y) + (v.z + v.w);
    }
    float s = (a0 + a1) + (a2 + a3);

    __shared__ float sm[256];
    sm[threadIdx.x] = s;
    __syncthreads();
    for (int o = 128; o > 0; o >>= 1) {
        if (threadIdx.x < o) sm[threadIdx.x] += sm[threadIdx.x + o];
        __syncthreads();
    }
    if (threadIdx.x == 0) d_partial[b * RBLK + blk] = sm[0];
}

// ---------------------------------------------------------------------------
// Kernel 2: fused mean-finalize + crop + mean-pad + bilinear resize.
// Block prologue: warps 0/1 reduce the partials of the <=2 batches this block
// touches (74 floats each, L2-hot). Then one thread per output pixel.
// ---------------------------------------------------------------------------
__global__ void bilinear_kernel(const float* __restrict__ im,
                                const float* __restrict__ pos,
                                const float* __restrict__ szs,
                                float* __restrict__ out) {
    __shared__ float s_mean[2];

    const int first = blockIdx.x * blockDim.x;
    const int last  = min(first + (int)blockDim.x - 1, TOTAL - 1);
    const int b0 = first / PIX_PER_B;
    const int b1 = last  / PIX_PER_B;

    const int w = threadIdx.x >> 5;
    const int l = threadIdx.x & 31;
    if (w < 2) {
        const int bb = (w == 0) ? b0 : b1;
        const float* pp = &d_partial[bb * RBLK];
        float s = pp[l] + pp[l + 32];               /* 64 of 74 */
        if (l < RBLK - 64) s += pp[l + 64];         /* remaining 10 */
        #pragma unroll
        for (int o = 16; o > 0; o >>= 1) s += __shfl_down_sync(0xffffffffu, s, o);
        if (l == 0) s_mean[w] = s * (1.0f / (float)PER_B);
    }
    __syncthreads();

    const int idx = first + threadIdx.x;
    if (idx >= TOTAL) return;

    int ox = idx % OUT;
    int t  = idx / OUT;
    int oy = t % OUT;
    t /= OUT;
    int c = t % NC;
    int b = t / NC;

    const float sz    = __ldg(&szs[b]);
    const float half  = (sz + 1.0f) * 0.5f;
    const float xmin  = rintf(__ldg(&pos[2 * b + 0]) - half);  /* round-half-even = jnp.round */
    const float ymin  = rintf(__ldg(&pos[2 * b + 1]) - half);
    const float scale = sz / (float)OUT;
    const float szm1  = sz - 1.0f;
    const float avg   = (b == b0) ? s_mean[0] : s_mean[1];

    float sx = fminf(fmaxf(((float)ox + 0.5f) * scale - 0.5f, 0.0f), szm1);
    float lx = floorf(sx);
    float wx = sx - lx;
    float hx = fminf(lx + 1.0f, szm1);

    float sy = fminf(fmaxf(((float)oy + 0.5f) * scale - 0.5f, 0.0f), szm1);
    float ly = floorf(sy);
    float wy = sy - ly;
    float hy = fminf(ly + 1.0f, szm1);

    float y0 = ly + ymin, y1 = hy + ymin;
    float x0 = lx + xmin, x1 = hx + xmin;

    const float* base = im + ((size_t)b * NC + c) * (size_t)(IH * IW);

    auto gather = [&](float yf, float xf) -> float {
        bool valid = (yf >= 0.0f) & (yf <= (float)(IH - 1)) &
                     (xf >= 0.0f) & (xf <= (float)(IW - 1));
        int yc = (int)fminf(fmaxf(yf, 0.0f), (float)(IH - 1));
        int xc = (int)fminf(fmaxf(xf, 0.0f), (float)(IW - 1));
        float pix = __ldg(&base[yc * IW + xc]);     /* clamped addr always in-bounds */
        return valid ? pix : avg;
    };

    float v00 = gather(y0, x0);
    float v01 = gather(y0, x1);
    float v10 = gather(y1, x0);
    float v11 = gather(y1, x1);

    float top = v00 * (1.0f - wx) + v01 * wx;
    float bot = v10 * (1.0f - wx) + v11 * wx;
    out[idx]  = top * (1.0f - wy) + bot * wy;
}

// ---------------------------------------------------------------------------
extern "C" void kernel_launch(void* const* d_in, const int* in_sizes, int n_in,
                              void* d_out, int out_size) {
    const float* im  = (const float*)d_in[0];
    const float* pos = (const float*)d_in[1];
    const float* szs = (const float*)d_in[2];
    float* out = (float*)d_out;

    reduce_kernel<<<dim3(RBLK, NB), 256>>>(im);
    bilinear_kernel<<<(TOTAL + 255) / 256, 256>>>(im, pos, szs, out);
}

// round 5
// speedup vs baseline: 1.4077x; 1.2880x over previous
#include <cuda_runtime.h>

#define NB 16
#define NC 3
#define IH 720
#define IW 1280
#define OUT 255
#define PER_B (NC*IH*IW)          /* 2764800 floats per batch image */
#define PER_B4 (PER_B/4)          /* 691200 float4 per batch image */
#define RBLK 74                   /* reduction blocks per batch -> 1184 = 8*148 total */

__device__ float d_partial[NB * RBLK];

// ---------------------------------------------------------------------------
// Kernel 1: per-batch partial sums. grid = (RBLK, NB) = 1184 blocks, block=256.
// ~75% DRAM is the observed plateau; left as-is.
// ---------------------------------------------------------------------------
__global__ void reduce_kernel(const float* __restrict__ im) {
    const int b   = blockIdx.y;
    const int blk = blockIdx.x;
    const float4* __restrict__ p = (const float4*)(im + (size_t)b * PER_B);

    const int stride = RBLK * 256;            /* 18944 */
    int i = blk * 256 + threadIdx.x;

    float a0 = 0.f, a1 = 0.f, a2 = 0.f, a3 = 0.f;
    for (; i + 3 * stride < PER_B4; i += 4 * stride) {
        float4 v0 = p[i];
        float4 v1 = p[i + stride];
        float4 v2 = p[i + 2 * stride];
        float4 v3 = p[i + 3 * stride];
        a0 += (v0.x + v0.y) + (v0.z + v0.w);
        a1 += (v1.x + v1.y) + (v1.z + v1.w);
        a2 += (v2.x + v2.y) + (v2.z + v2.w);
        a3 += (v3.x + v3.y) + (v3.z + v3.w);
    }
    for (; i < PER_B4; i += stride) {
        float4 v = p[i];
        a0 += (v.x + v.y) + (v.z + v.w);
    }
    float s = (a0 + a1) + (a2 + a3);

    __shared__ float sm[256];
    sm[threadIdx.x] = s;
    __syncthreads();
    for (int o = 128; o > 0; o >>= 1) {
        if (threadIdx.x < o) sm[threadIdx.x] += sm[threadIdx.x + o];
        __syncthreads();
    }
    if (threadIdx.x == 0) d_partial[b * RBLK + blk] = sm[0];
}

// ---------------------------------------------------------------------------
// Kernel 2: fused mean-finalize + crop + mean-pad + bilinear resize.
// grid = (OUT, NB): block = one output row of one batch, all 3 channels.
// threadIdx.x = ox. Zero div/mod; coords computed once, reused across c.
// ---------------------------------------------------------------------------
__global__ void bilinear_kernel(const float* __restrict__ im,
                                const float* __restrict__ pos,
                                const float* __restrict__ szs,
                                float* __restrict__ out) {
    const int oy = blockIdx.x;
    const int b  = blockIdx.y;

    __shared__ float s_mean;
    if (threadIdx.x < 32) {
        const int l = threadIdx.x;
        const float* pp = &d_partial[b * RBLK];
        float s = pp[l] + pp[l + 32];
        if (l < RBLK - 64) s += pp[l + 64];
        #pragma unroll
        for (int o = 16; o > 0; o >>= 1) s += __shfl_down_sync(0xffffffffu, s, o);
        if (l == 0) s_mean = s * (1.0f / (float)PER_B);
    }
    __syncthreads();

    const int ox = threadIdx.x;
    if (ox >= OUT) return;

    const float sz    = __ldg(&szs[b]);
    const float half  = (sz + 1.0f) * 0.5f;
    const float xmin  = rintf(__ldg(&pos[2 * b + 0]) - half);  /* round-half-even = jnp.round */
    const float ymin  = rintf(__ldg(&pos[2 * b + 1]) - half);
    const float scale = sz / (float)OUT;
    const float szm1  = sz - 1.0f;
    const float avg   = s_mean;

    float sx = fminf(fmaxf(((float)ox + 0.5f) * scale - 0.5f, 0.0f), szm1);
    float lx = floorf(sx);
    float wx = sx - lx;
    float hx = fminf(lx + 1.0f, szm1);

    float sy = fminf(fmaxf(((float)oy + 0.5f) * scale - 0.5f, 0.0f), szm1);
    float ly = floorf(sy);
    float wy = sy - ly;
    float hy = fminf(ly + 1.0f, szm1);

    float y0 = ly + ymin, y1 = hy + ymin;
    float x0 = lx + xmin, x1 = hx + xmin;

    /* validity + clamped integer coords: computed ONCE, shared by 3 channels */
    bool vy0 = (y0 >= 0.0f) & (y0 <= (float)(IH - 1));
    bool vy1 = (y1 >= 0.0f) & (y1 <= (float)(IH - 1));
    bool vx0 = (x0 >= 0.0f) & (x0 <= (float)(IW - 1));
    bool vx1 = (x1 >= 0.0f) & (x1 <= (float)(IW - 1));
    int iy0 = (int)fminf(fmaxf(y0, 0.0f), (float)(IH - 1));
    int iy1 = (int)fminf(fmaxf(y1, 0.0f), (float)(IH - 1));
    int ix0 = (int)fminf(fmaxf(x0, 0.0f), (float)(IW - 1));
    int ix1 = (int)fminf(fmaxf(x1, 0.0f), (float)(IW - 1));
    bool v00 = vy0 & vx0, v01 = vy0 & vx1, v10 = vy1 & vx0, v11 = vy1 & vx1;

    const int o00 = iy0 * IW + ix0;
    const int o01 = iy0 * IW + ix1;
    const int o10 = iy1 * IW + ix0;
    const int o11 = iy1 * IW + ix1;

    const float* base = im + (size_t)b * PER_B;
    float* orow = out + ((size_t)(b * NC) * OUT + oy) * OUT + ox;

    const float omwx = 1.0f - wx, omwy = 1.0f - wy;

    #pragma unroll
    for (int c = 0; c < NC; c++) {
        const float* pl = base + c * (IH * IW);
        float p00 = v00 ? __ldg(&pl[o00]) : avg;
        float p01 = v01 ? __ldg(&pl[o01]) : avg;
        float p10 = v10 ? __ldg(&pl[o10]) : avg;
        float p11 = v11 ? __ldg(&pl[o11]) : avg;
        float top = p00 * omwx + p01 * wx;
        float bot = p10 * omwx + p11 * wx;
        orow[c * (OUT * OUT)] = top * omwy + bot * wy;
    }
}

// ---------------------------------------------------------------------------
extern "C" void kernel_launch(void* const* d_in, const int* in_sizes, int n_in,
                              void* d_out, int out_size) {
    const float* im  = (const float*)d_in[0];
    const float* pos = (const float*)d_in[1];
    const float* szs = (const float*)d_in[2];
    float* out = (float*)d_out;

    reduce_kernel<<<dim3(RBLK, NB), 256>>>(im);
    bilinear_kernel<<<dim3(OUT, NB), 256>>>(im, pos, szs, out);
}